// round 2
// baseline (speedup 1.0000x reference)
#include <cuda_runtime.h>
#include <cstdint>
#include <cstddef>

#define GRID   128
#define TPB    256
#define BATCH  128
#define SEQ    256
#define UNITS  512

// Layer geometry
#define N0 269
#define D0 333
#define KP0 167   // ceil(334/2)
#define N1 179
#define D1 448
#define KP1 224
#define N2 64
#define D2 243
#define KP2 122   // ceil(244/2)

// CTA partition: 60 / 56 / 12 (proportional to FLOPs), each layer split
// into (ngroups x 4 batch-groups of 32 rows)
#define L0_CTAS 60
#define L1_CTAS 56
#define NG_0 15
#define NG_1 14
#define NG_2 3

// Shared memory layout (floats)
#define WS_MAX   24048            // max per-CTA packed weight slice (18*167*8)
#define XCS_MAX  14784            // 224 kp-rows * 66 floats (33 float2, padded)
#define BIAS_MAX 96
#define SMEM_FLOATS (WS_MAX + XCS_MAX + BIAS_MAX)
#define SMEM_BYTES  (SMEM_FLOATS * 4)

#define YSZ   (BATCH * SEQ * 64)
#define HSZ   (BATCH * UNITS)

// ---------------- device scratch (static: no allocation) ----------------
__device__ float g_pw0[N0 * KP0 * 8];
__device__ float g_pw1[N1 * KP1 * 8];
__device__ float g_pw2[N2 * KP2 * 8];
__device__ float4 g_pb[UNITS];
__device__ float g_h[2][HSZ];
__device__ unsigned g_arrive;
__device__ volatile unsigned g_release;

// ---------------- helpers ----------------
static __device__ __forceinline__ unsigned long long ffma2(
    unsigned long long a, unsigned long long b, unsigned long long c) {
    unsigned long long d;
    asm("fma.rn.f32x2 %0, %1, %2, %3;" : "=l"(d) : "l"(a), "l"(b), "l"(c));
    return d;
}
static __device__ __forceinline__ float f2lo(unsigned long long v) {
    return __uint_as_float((unsigned)(v & 0xffffffffull));
}
static __device__ __forceinline__ float f2hi(unsigned long long v) {
    return __uint_as_float((unsigned)(v >> 32));
}

// Sense-free monotonic grid barrier. Requires all GRID CTAs co-resident
// (guaranteed: 1 CTA/SM via smem footprint; 128 CTAs <= 148 SMs on B200).
static __device__ __forceinline__ void grid_barrier(unsigned target) {
    __syncthreads();
    if (threadIdx.x == 0) {
        __threadfence();
        unsigned a = atomicAdd(&g_arrive, 1u) + 1u;
        if (a == target) {
            atomicExch((unsigned*)&g_release, target);
        } else {
            while (g_release < target) { __nanosleep(64); }
        }
        __threadfence();
    }
    __syncthreads();
}

// ---------------- per-layer persistent worker ----------------
template<int LAYER, int N, int D, int KP, int NG, int OFF>
static __device__ void run_layer(int idx,
                                 const float* __restrict__ x,
                                 float* __restrict__ out, int out_size,
                                 float* ws, float* xcs_f, float4* bias_s,
                                 const float* pw) {
    const int ng = idx >> 2;
    const int bg = idx & 3;
    const int js = (N * ng) / NG;
    const int je = (N * (ng + 1)) / NG;
    const int b0 = bg * 32;
    const int lane = threadIdx.x & 31;
    const int wid  = threadIdx.x >> 5;
    constexpr int DP = (D + 1) & ~1;

    // Copy this CTA's packed weight slice + biases into SMEM (once).
    {
        const float4* src = (const float4*)pw + (size_t)js * KP * 2;
        float4* dst = (float4*)ws;
        const int cnt = (je - js) * KP * 2;
        for (int i = threadIdx.x; i < cnt; i += TPB) dst[i] = src[i];
        if (threadIdx.x < (je - js)) bias_s[threadIdx.x] = g_pb[OFF + js + threadIdx.x];
    }

    float* hout = (out_size >= YSZ + HSZ) ? (out + YSZ) : (float*)0;
    float* yout = (out_size >= YSZ) ? out : (float*)0;

    for (int p = 0; p < 258; ++p) {
        const int step = p - LAYER;
        if (step >= 0 && step < SEQ) {
            const float* __restrict__ hprev = g_h[(p + 1) & 1];
            float* __restrict__ hcur = g_h[p & 1];

            // ---- stage xc into SMEM (pair-major, stride-33 float2, conflict-free) ----
            #pragma unroll
            for (int r = 0; r < 4; ++r) {
                const int bl  = wid * 4 + r;
                const int bgl = b0 + bl;
                if (LAYER == 0) {
                    const float* xb = x + ((size_t)bgl * SEQ + step) * 64;
                    const float* hb = hprev + (size_t)bgl * UNITS;
                    for (int k = lane; k < DP; k += 32) {
                        float v;
                        if (k < 64)      v = __ldg(xb + k);
                        else if (k < D)  v = __ldcg(hb + (k - 64));
                        else             v = 0.f;
                        xcs_f[(k >> 1) * 66 + bl * 2 + (k & 1)] = v;
                    }
                } else {
                    const float* hb = hprev + (size_t)bgl * UNITS + (LAYER == 1 ? 0 : 269);
                    for (int k = lane; k < DP; k += 32) {
                        float v = (k < D) ? __ldcg(hb + k) : 0.f;
                        xcs_f[(k >> 1) * 66 + bl * 2 + (k & 1)] = v;
                    }
                }
            }
            __syncthreads();

            // ---- compute: per warp a set of neurons, f32x2 along k, lane=batch ----
            const unsigned long long* xp = ((const unsigned long long*)xcs_f) + lane;
            for (int j = js + wid; j < je; j += 8) {
                const ulonglong2* wp = ((const ulonglong2*)ws) + (size_t)(j - js) * KP * 2;
                unsigned long long a1 = 0, a2 = 0, aa = 0, ab = 0;
                #pragma unroll 4
                for (int q = 0; q < KP; ++q) {
                    unsigned long long xv = xp[q * 33];
                    ulonglong2 wA = wp[2 * q];
                    ulonglong2 wB = wp[2 * q + 1];
                    a1 = ffma2(xv, wA.x, a1);
                    a2 = ffma2(xv, wA.y, a2);
                    aa = ffma2(xv, wB.x, aa);
                    ab = ffma2(xv, wB.y, ab);
                }
                float s1 = f2lo(a1) + f2hi(a1);
                float s2 = f2lo(a2) + f2hi(a2);
                float st = (f2lo(aa) + f2hi(aa)) + (f2lo(ab) + f2hi(ab));
                float4 bv = bias_s[j - js];
                float ff1 = tanhf(s1 + bv.x);
                float ff2 = tanhf(s2 + bv.y);
                float t = 1.f / (1.f + __expf(-(st + bv.z)));
                float o = ff1 + t * (ff2 - ff1);
                const int bgl = b0 + lane;
                hcur[(size_t)bgl * UNITS + OFF + j] = o;
                if (LAYER == 2) {
                    if (yout) yout[((size_t)bgl * SEQ + step) * 64 + j] = tanhf(o);
                }
                if (step == SEQ - 1 && hout) {
                    hout[(size_t)bgl * UNITS + OFF + j] = o;
                }
            }
        }
        grid_barrier((unsigned)(p + 1) * GRID);
    }
}

// ---------------- kernels ----------------
__global__ void __launch_bounds__(TPB, 1) cfc_kernel(const float* __restrict__ x,
                                                     float* __restrict__ out,
                                                     int out_size) {
    extern __shared__ float smem[];
    float*  ws     = smem;
    float*  xcs_f  = smem + WS_MAX;
    float4* bias_s = (float4*)(smem + WS_MAX + XCS_MAX);
    const int cta = blockIdx.x;
    if (cta < L0_CTAS)
        run_layer<0, N0, D0, KP0, NG_0, 0  >(cta,            x, out, out_size, ws, xcs_f, bias_s, g_pw0);
    else if (cta < L0_CTAS + L1_CTAS)
        run_layer<1, N1, D1, KP1, NG_1, 269>(cta - L0_CTAS,  x, out, out_size, ws, xcs_f, bias_s, g_pw1);
    else
        run_layer<2, N2, D2, KP2, NG_2, 448>(cta - (L0_CTAS + L1_CTAS), x, out, out_size, ws, xcs_f, bias_s, g_pw2);
}

// Pack weights as [j][kp][8]: {w1m k0,k1, w2m k0,k1, wa k0,k1, wb k0,k1},
// mask folded into w1/w2, zero padding for k >= d.
__global__ void pack_kernel(const float* __restrict__ w1, const float* __restrict__ w2,
                            const float* __restrict__ wa, const float* __restrict__ wb,
                            const float* __restrict__ mask,
                            int n, int d, int kp, int sel) {
    float* dst = (sel == 0) ? g_pw0 : ((sel == 1) ? g_pw1 : g_pw2);
    int idx = blockIdx.x * blockDim.x + threadIdx.x;
    if (idx >= n * kp) return;
    int j = idx / kp;
    int pq = idx - j * kp;
    int k0 = 2 * pq, k1 = k0 + 1;
    const int r = j * d;
    float v10 = 0, v11 = 0, v20 = 0, v21 = 0, va0 = 0, va1 = 0, vb0 = 0, vb1 = 0;
    if (k0 < d) {
        float m0 = mask[r + k0];
        v10 = w1[r + k0] * m0; v20 = w2[r + k0] * m0;
        va0 = wa[r + k0];      vb0 = wb[r + k0];
    }
    if (k1 < d) {
        float m1 = mask[r + k1];
        v11 = w1[r + k1] * m1; v21 = w2[r + k1] * m1;
        va1 = wa[r + k1];      vb1 = wb[r + k1];
    }
    float4* o = (float4*)(dst + (size_t)idx * 8);
    o[0] = make_float4(v10, v11, v20, v21);
    o[1] = make_float4(va0, va1, vb0, vb1);
}

__global__ void init_kernel(const float* __restrict__ h0,
                            const float* b1_0, const float* b2_0, const float* ba_0, const float* bb_0,
                            const float* b1_1, const float* b2_1, const float* ba_1, const float* bb_1,
                            const float* b1_2, const float* b2_2, const float* ba_2, const float* bb_2) {
    int gid = blockIdx.x * blockDim.x + threadIdx.x;
    if (gid == 0) { g_arrive = 0; g_release = 0; }
    if (gid < HSZ) {
        float v = h0[gid];
        g_h[0][gid] = v;
        g_h[1][gid] = v;
    }
    if (gid < UNITS) {
        int j; const float *b1, *b2, *ba, *bb;
        if (gid < 269)      { j = gid;       b1 = b1_0; b2 = b2_0; ba = ba_0; bb = bb_0; }
        else if (gid < 448) { j = gid - 269; b1 = b1_1; b2 = b2_1; ba = ba_1; bb = bb_1; }
        else                { j = gid - 448; b1 = b1_2; b2 = b2_2; ba = ba_2; bb = bb_2; }
        g_pb[gid] = make_float4(b1[j], b2[j], ba[j] + bb[j], 0.f);
    }
}

// ---------------- entry point ----------------
extern "C" void kernel_launch(void* const* d_in, const int* in_sizes, int n_in,
                              void* d_out, int out_size) {
    // metadata order: x, dt, h0, then per layer l: w1,w2,wa,wb,b1,b2,ba,bb,mask
    const float* x    = (const float*)d_in[0];
    const float* h0   = (const float*)d_in[2];
    const float* w1_0 = (const float*)d_in[3];
    const float* w2_0 = (const float*)d_in[4];
    const float* wa_0 = (const float*)d_in[5];
    const float* wb_0 = (const float*)d_in[6];
    const float* b1_0 = (const float*)d_in[7];
    const float* b2_0 = (const float*)d_in[8];
    const float* ba_0 = (const float*)d_in[9];
    const float* bb_0 = (const float*)d_in[10];
    const float* mk_0 = (const float*)d_in[11];
    const float* w1_1 = (const float*)d_in[12];
    const float* w2_1 = (const float*)d_in[13];
    const float* wa_1 = (const float*)d_in[14];
    const float* wb_1 = (const float*)d_in[15];
    const float* b1_1 = (const float*)d_in[16];
    const float* b2_1 = (const float*)d_in[17];
    const float* ba_1 = (const float*)d_in[18];
    const float* bb_1 = (const float*)d_in[19];
    const float* mk_1 = (const float*)d_in[20];
    const float* w1_2 = (const float*)d_in[21];
    const float* w2_2 = (const float*)d_in[22];
    const float* wa_2 = (const float*)d_in[23];
    const float* wb_2 = (const float*)d_in[24];
    const float* b1_2 = (const float*)d_in[25];
    const float* b2_2 = (const float*)d_in[26];
    const float* ba_2 = (const float*)d_in[27];
    const float* bb_2 = (const float*)d_in[28];
    const float* mk_2 = (const float*)d_in[29];

    cudaFuncSetAttribute(cfc_kernel, cudaFuncAttributeMaxDynamicSharedMemorySize, SMEM_BYTES);

    init_kernel<<<256, 256>>>(h0,
                              b1_0, b2_0, ba_0, bb_0,
                              b1_1, b2_1, ba_1, bb_1,
                              b1_2, b2_2, ba_2, bb_2);
    pack_kernel<<<(N0 * KP0 + 255) / 256, 256>>>(w1_0, w2_0, wa_0, wb_0, mk_0, N0, D0, KP0, 0);
    pack_kernel<<<(N1 * KP1 + 255) / 256, 256>>>(w1_1, w2_1, wa_1, wb_1, mk_1, N1, D1, KP1, 1);
    pack_kernel<<<(N2 * KP2 + 255) / 256, 256>>>(w1_2, w2_2, wa_2, wb_2, mk_2, N2, D2, KP2, 2);

    cfc_kernel<<<GRID, TPB, SMEM_BYTES>>>(x, (float*)d_out, out_size);
}